// round 13
// baseline (speedup 1.0000x reference)
#include <cuda_runtime.h>
#include <cuda_fp16.h>

#define NN 100000
#define NE 800000
#define DD 300
#define NG 64
#define NB 98            // scan blocks (98 * 1024 >= NN)
#define WV 10000         // word vocab
#define AV 41            // atom vocab

// ---------------- scratch (device globals; no allocation allowed) ----------
__device__ int     g_cnt[NN];        // src counts (rowptr);  self-reset in scan3
__device__ int     g_cnt2[NN];       // dst counts (dinv);    self-reset in scan3
__device__ int     g_rowptr[NN + 1];
__device__ int     g_wpos[NN];
__device__ int     g_off[NE];        // byte offset of gathered row (dst*128)
__device__ float   g_dinv[NN];
__device__ float   g_rdinv[NN];
__device__ int     g_bsum[NB];
__device__ int     g_boff[NB];
__device__ __half2 g_hA[(size_t)NN * 32];   // 12.8 MB (q rows, 64 fp16)
__device__ __half2 g_hB[(size_t)NN * 32];   // 12.8 MB
__device__ __half2 g_Qw[WV * 32];    // word buckets, fp16
__device__ float   g_Qa[AV * 64];    // atom buckets, fp32
__device__ float   g_Msum[NG * DD];
__device__ float   g_usum[2 * NG];   // [0..63]=u1=PÂ1, [64..127]=u2=PÂ²1
__device__ int     g_gcnt[NG];
__device__ float   g_T1[NG * DD];
__device__ float   g_T2[NG * DD];

// ---------------- CSR build (reverse: by src) --------------------------------

__global__ void hist_kernel(const int* __restrict__ ei) {
    int e = blockIdx.x * blockDim.x + threadIdx.x;
    if (e >= NE) return;
    atomicAdd(&g_cnt[ei[e]], 1);        // src -> rowptr
    atomicAdd(&g_cnt2[ei[NE + e]], 1);  // dst -> degree norm
}

__global__ void scan1_kernel() {
    __shared__ int sh[1024];
    int i = blockIdx.x * 1024 + threadIdx.x;
    int c = 0;
    if (i < NN) {
        c = g_cnt[i];
        int cd = g_cnt2[i];
        g_dinv[i]  = rsqrtf((float)(cd + 1));   // +1 self loop
        g_rdinv[i] = sqrtf((float)(cd + 1));
    }
    sh[threadIdx.x] = c;
    __syncthreads();
    for (int off = 512; off > 0; off >>= 1) {
        if (threadIdx.x < off) sh[threadIdx.x] += sh[threadIdx.x + off];
        __syncthreads();
    }
    if (threadIdx.x == 0) g_bsum[blockIdx.x] = sh[0];
}

__global__ void scan2_kernel() {
    __shared__ int sh[NB];
    int tid = threadIdx.x;
    if (tid < NB) sh[tid] = g_bsum[tid];
    __syncthreads();
    if (tid == 0) {
        int run = 0;
        for (int b = 0; b < NB; ++b) { g_boff[b] = run; run += sh[b]; }
        g_rowptr[NN] = run;   // == NE
    }
    for (int i = tid; i < NG * DD; i += blockDim.x) g_Msum[i] = 0.f;
    if (tid < 2 * NG) g_usum[tid] = 0.f;
    if (tid < NG)     g_gcnt[tid] = 0;
}

__global__ void scan3_kernel() {
    __shared__ int sh[1024];
    int tid = threadIdx.x;
    int i = blockIdx.x * 1024 + tid;
    int c = (i < NN) ? g_cnt[i] : 0;
    sh[tid] = c;
    __syncthreads();
    for (int off = 1; off < 1024; off <<= 1) {
        int v = (tid >= off) ? sh[tid - off] : 0;
        __syncthreads();
        sh[tid] += v;
        __syncthreads();
    }
    if (i < NN) {
        int excl = g_boff[blockIdx.x] + sh[tid] - c;
        g_rowptr[i] = excl;
        g_wpos[i]   = excl;
        g_cnt[i]    = 0;
        g_cnt2[i]   = 0;
    }
}

// fused: edge scatter + q0 init (z0 = dinv * one-hot(batch)) + gcnt + zero Qw/Qa
#define EDGE_BLOCKS ((NE + 255) / 256)
#define Q0_BLOCKS   ((NN * 8 + 255) / 256)
#define ZQW 80000                      // Qw uint4 count (10000*64*2/16)
#define ZQA 656                        // Qa uint4 count (41*64*4/16)
#define ZQ_BLOCKS   ((ZQW + ZQA + 255) / 256)
__global__ void scatter_init_kernel(const int* __restrict__ ei,
                                    const int* __restrict__ batch) {
    int b = blockIdx.x;
    if (b < EDGE_BLOCKS) {
        int e = b * 256 + threadIdx.x;
        if (e >= NE) return;
        int src = ei[e];
        int dst = ei[NE + e];
        int pos = atomicAdd(&g_wpos[src], 1);
        g_off[pos] = dst * 128;
    } else if (b < EDGE_BLOCKS + Q0_BLOCKS) {
        int idx = (b - EDGE_BLOCKS) * 256 + threadIdx.x;
        if (idx >= NN * 8) return;
        int i = idx >> 3, sub = idx & 7;
        int bg = batch[i];
        union { uint4 v; __half h[8]; } u;
        u.v = make_uint4(0, 0, 0, 0);
        int rel = bg - sub * 8;
        if (rel >= 0 && rel < 8) u.h[rel] = __float2half(g_dinv[i]);
        ((uint4*)g_hA)[i * 8 + sub] = u.v;
        if (sub == 0) atomicAdd(&g_gcnt[bg], 1);
    } else {
        int idx = (b - EDGE_BLOCKS - Q0_BLOCKS) * 256 + threadIdx.x;
        uint4 z = make_uint4(0, 0, 0, 0);
        if (idx < ZQW) ((uint4*)g_Qw)[idx] = z;
        else if (idx < ZQW + ZQA) ((uint4*)g_Qa)[idx - ZQW] = z;
    }
}

// one hop of q through A^T on pre-scaled rows (z = dinv .* q), 64-wide fp16.
// warp per node; 4 edges per iteration via 8-lane groups + shuffle reduce.
// last=0: out = dinv^2 * (sum + self)   (z for next hop)
// last=1: out = dinv   * (sum + self)   (true q3)
__global__ void hop_kernel(const __half2* __restrict__ in,
                           __half2* __restrict__ out, int last) {
    int i = blockIdx.x * 4 + (threadIdx.x >> 5);
    int lane = threadIdx.x & 31;
    int grp = lane >> 3, sub = lane & 7;
    int beg = g_rowptr[i], end = g_rowptr[i + 1];
    const char* base = (const char*)in + sub * 16;
    __half2 a0 = __float2half2_rn(0.f), a1 = a0, a2 = a0, a3 = a0;
    int n4 = (end - beg) & ~3;
    for (int k = 0; k < n4; k += 4) {
        int o = g_off[beg + k + grp];
        uint4 v = *(const uint4*)(base + o);
        a0 = __hadd2(a0, *(const __half2*)&v.x);
        a1 = __hadd2(a1, *(const __half2*)&v.y);
        a2 = __hadd2(a2, *(const __half2*)&v.z);
        a3 = __hadd2(a3, *(const __half2*)&v.w);
    }
    int r = beg + n4 + grp;
    if (r < end) {
        int o = g_off[r];
        uint4 v = *(const uint4*)(base + o);
        a0 = __hadd2(a0, *(const __half2*)&v.x);
        a1 = __hadd2(a1, *(const __half2*)&v.y);
        a2 = __hadd2(a2, *(const __half2*)&v.z);
        a3 = __hadd2(a3, *(const __half2*)&v.w);
    }
    // reduce the 4 lane-groups (lane, lane+8, lane+16, lane+24)
    a0 = __hadd2(a0, __shfl_down_sync(0xffffffffu, a0, 16));
    a1 = __hadd2(a1, __shfl_down_sync(0xffffffffu, a1, 16));
    a2 = __hadd2(a2, __shfl_down_sync(0xffffffffu, a2, 16));
    a3 = __hadd2(a3, __shfl_down_sync(0xffffffffu, a3, 16));
    a0 = __hadd2(a0, __shfl_down_sync(0xffffffffu, a0, 8));
    a1 = __hadd2(a1, __shfl_down_sync(0xffffffffu, a1, 8));
    a2 = __hadd2(a2, __shfl_down_sync(0xffffffffu, a2, 8));
    a3 = __hadd2(a3, __shfl_down_sync(0xffffffffu, a3, 8));
    if (lane < 8) {
        uint4 sv = *(const uint4*)(base + i * 128);
        float di = g_dinv[i];
        float f = last ? di : di * di;
        float2 s0 = __half22float2(*(__half2*)&sv.x);
        float2 s1 = __half22float2(*(__half2*)&sv.y);
        float2 s2 = __half22float2(*(__half2*)&sv.z);
        float2 s3 = __half22float2(*(__half2*)&sv.w);
        float2 f0 = __half22float2(a0), f1 = __half22float2(a1);
        float2 f2 = __half22float2(a2), f3 = __half22float2(a3);
        uint4 o;
        *(__half2*)&o.x = __float22half2_rn(make_float2(f*(f0.x+s0.x), f*(f0.y+s0.y)));
        *(__half2*)&o.y = __float22half2_rn(make_float2(f*(f1.x+s1.x), f*(f1.y+s1.y)));
        *(__half2*)&o.z = __float22half2_rn(make_float2(f*(f2.x+s2.x), f*(f2.y+s2.y)));
        *(__half2*)&o.w = __float22half2_rn(make_float2(f*(f3.x+s3.x), f*(f3.y+s3.y)));
        *(uint4*)((char*)out + i * 128 + sub * 16) = o;
    }
}

// column sums of true q = z * rdinv: u[g] = sum_i z[i][g] * rdinv[i]
#define CS_ROWS 500
__global__ void colsum_kernel(const __half2* __restrict__ z, float* __restrict__ u) {
    __shared__ float sm[8][64];
    int gp = threadIdx.x & 31, rg = threadIdx.x >> 5;
    int i0 = blockIdx.x * CS_ROWS;
    int i1 = i0 + CS_ROWS; if (i1 > NN) i1 = NN;
    float2 acc = make_float2(0.f, 0.f);
    for (int i = i0 + rg; i < i1; i += 8) {
        float2 v = __half22float2(z[(size_t)i * 32 + gp]);
        float rd = g_rdinv[i];
        acc.x += v.x * rd; acc.y += v.y * rd;
    }
    sm[rg][2 * gp] = acc.x; sm[rg][2 * gp + 1] = acc.y;
    __syncthreads();
    if (rg == 0) {
        float s0 = 0.f, s1 = 0.f;
        #pragma unroll
        for (int r2 = 0; r2 < 8; ++r2) { s0 += sm[r2][2 * gp]; s1 += sm[r2][2 * gp + 1]; }
        atomicAdd(&u[2 * gp], s0);
        atomicAdd(&u[2 * gp + 1], s1);
    }
}

// scatter q3 into vocab buckets: Qw[w][g] += q3[i][g], Qa[a][g] += q3[i][g]
#define VCH 512
__global__ void vscatter_kernel(const __half2* __restrict__ q3,
                                const int* __restrict__ x) {
    __shared__ float sQa[AV * 64];
    for (int k = threadIdx.x; k < AV * 64; k += 256) sQa[k] = 0.f;
    __syncthreads();
    int gp = threadIdx.x & 31, ns = threadIdx.x >> 5;
    int i0 = blockIdx.x * VCH;
    int i1 = i0 + VCH; if (i1 > NN) i1 = NN;
    for (int i = i0 + ns; i < i1; i += 8) {
        __half2 q = q3[(size_t)i * 32 + gp];
        int a = x[2 * i], w = x[2 * i + 1];
        atomicAdd(&g_Qw[w * 32 + gp], q);            // fp16x2 red, low contention
        float2 f = __half22float2(q);
        atomicAdd(&sQa[a * 64 + 2 * gp],     f.x);   // smem, high contention ok
        atomicAdd(&sQa[a * 64 + 2 * gp + 1], f.y);
    }
    __syncthreads();
    for (int k = threadIdx.x; k < AV * 64; k += 256) atomicAdd(&g_Qa[k], sQa[k]);
}

// Msum = Qw @ wt + Qa @ at   (64 x 300, K = 10000 / 41)
#define WPB 63
__global__ void vgemm_kernel(const float* __restrict__ wt,
                             const float* __restrict__ at) {
    __shared__ float qs[64];
    int d = threadIdx.x;   // 0..319, active < 300
    float acc[64];
    #pragma unroll
    for (int g = 0; g < 64; ++g) acc[g] = 0.f;
    if (blockIdx.x < 160) {
        int w0 = blockIdx.x * WPB;
        int w1 = w0 + WPB; if (w1 > WV) w1 = WV;
        for (int w = w0; w < w1; ++w) {
            __syncthreads();
            if (threadIdx.x < 32) {
                float2 f = __half22float2(g_Qw[w * 32 + threadIdx.x]);
                qs[2 * threadIdx.x] = f.x; qs[2 * threadIdx.x + 1] = f.y;
            }
            __syncthreads();
            if (d < DD) {
                float hv = wt[w * DD + d];
                #pragma unroll
                for (int g = 0; g < 64; ++g) acc[g] += qs[g] * hv;
            }
        }
    } else {
        for (int a = 0; a < AV; ++a) {
            __syncthreads();
            if (threadIdx.x < 64) qs[threadIdx.x] = g_Qa[a * 64 + threadIdx.x];
            __syncthreads();
            if (d < DD) {
                float hv = at[a * DD + d];
                #pragma unroll
                for (int g = 0; g < 64; ++g) acc[g] += qs[g] * hv;
            }
        }
    }
    if (d < DD) {
        #pragma unroll
        for (int g = 0; g < 64; ++g) atomicAdd(&g_Msum[g * DD + d], acc[g]);
    }
}

// epilogue GEMM step: out[g] = in[g]@W + coef[g]*b          (finalize=0)
//                     out[g] = in[g]@W/max(cnt,1)+(cnt>0)*b (finalize=1)
__global__ void mg_kernel(const float* __restrict__ in, float* __restrict__ outp,
                          const float* __restrict__ W, const float* __restrict__ bvec,
                          const float* __restrict__ coef, int finalize) {
    int g = blockIdx.x;
    int c = threadIdx.x;
    __shared__ float arow[DD];
    for (int k = c; k < DD; k += 320) arow[k] = in[g * DD + k];
    __syncthreads();
    if (c >= DD) return;
    float acc = 0.f;
    #pragma unroll 4
    for (int k = 0; k < DD; ++k) acc += arow[k] * W[k * DD + c];
    if (!finalize) {
        outp[g * DD + c] = acc + coef[g] * bvec[c];
    } else {
        int cnt = g_gcnt[g];
        float denom = (cnt > 0) ? (float)cnt : 1.f;
        float r = acc / denom;
        if (cnt > 0) r += bvec[c];
        outp[g * DD + c] = r;
    }
}

// ---------------- launch ----------------------------------------------------

extern "C" void kernel_launch(void* const* d_in, const int* in_sizes, int n_in,
                              void* d_out, int out_size) {
    const int*   x     = (const int*)d_in[0];     // [N,2]
    const int*   ei    = (const int*)d_in[1];     // [2,E]
    const int*   batch = (const int*)d_in[2];     // [N]
    const float* at    = (const float*)d_in[3];   // [41,300]
    const float* wt    = (const float*)d_in[4];   // [10000,300]
    const float* W     = (const float*)d_in[5];   // [300,300]
    const float* b     = (const float*)d_in[6];   // [300]
    float* out = (float*)d_out;

    __half2 *hA, *hB;
    float *T1, *T2, *Msum, *usum;
    cudaGetSymbolAddress((void**)&hA,   g_hA);
    cudaGetSymbolAddress((void**)&hB,   g_hB);
    cudaGetSymbolAddress((void**)&T1,   g_T1);
    cudaGetSymbolAddress((void**)&T2,   g_T2);
    cudaGetSymbolAddress((void**)&Msum, g_Msum);
    cudaGetSymbolAddress((void**)&usum, g_usum);

    // reverse-CSR build (by src); dinv from dst in-degree
    hist_kernel<<<(NE + 255) / 256, 256>>>(ei);                              // 0
    scan1_kernel<<<NB, 1024>>>();                                            // 1
    scan2_kernel<<<1, 256>>>();                                              // 2
    scan3_kernel<<<NB, 1024>>>();                                            // 3
    scatter_init_kernel<<<EDGE_BLOCKS + Q0_BLOCKS + ZQ_BLOCKS, 256>>>(ei, batch); // 4
    // q-hops: z0 -> z1 -> z2 -> q3 (column sums give u1 = PÂ1, u2 = PÂ²1)
    hop_kernel<<<NN / 4, 128>>>(hA, hB, 0);                                  // 5
    colsum_kernel<<<(NN + CS_ROWS - 1) / CS_ROWS, 256>>>(hB, usum);          // 6
    hop_kernel<<<NN / 4, 128>>>(hB, hA, 0);                                  // 7
    colsum_kernel<<<(NN + CS_ROWS - 1) / CS_ROWS, 256>>>(hA, usum + NG);     // 8
    hop_kernel<<<NN / 4, 128>>>(hA, hB, 1);                                  // 9 -> q3 in hB
    // factor through embedding tables: Msum = q3^T Ia at + q3^T Iw wt
    vscatter_kernel<<<(NN + VCH - 1) / VCH, 256>>>(hB, x);                   // 10
    vgemm_kernel<<<161, 320>>>(wt, at);                                      // 11
    // epilogue: ((Msum@W + u2⊗b)@W + u1⊗b)@W, then /cnt + b
    mg_kernel<<<NG, 320>>>(Msum, T1, W, b, usum + NG, 0);                    // 12
    mg_kernel<<<NG, 320>>>(T1,   T2, W, b, usum,      0);                    // 13
    mg_kernel<<<NG, 320>>>(T2,  out, W, b, usum,      1);                    // 14
}

// round 14
// speedup vs baseline: 1.0007x; 1.0007x over previous
#include <cuda_runtime.h>
#include <cuda_fp16.h>

#define NN 100000
#define NE 800000
#define DD 300
#define NG 64
#define NB 98            // scan blocks (98 * 1024 >= NN)
#define WV 10000         // word vocab
#define AV 41            // atom vocab

// ---------------- scratch (device globals; no allocation allowed) ----------
__device__ int     g_cnt[NN];        // src counts (rowptr);  self-reset in scan3
__device__ int     g_cnt2[NN];       // dst counts (dinv);    self-reset in scan3
__device__ int     g_rowptr[NN + 1];
__device__ int     g_wpos[NN];
__device__ int     g_off[NE];        // byte offset of gathered row (dst*128)
__device__ float   g_dinv[NN];
__device__ float   g_rdinv[NN];
__device__ int     g_bsum[NB];
__device__ int     g_boff[NB];
__device__ __half2 g_hA[(size_t)NN * 32];   // 12.8 MB (q rows, 64 fp16)
__device__ __half2 g_hB[(size_t)NN * 32];   // 12.8 MB
__device__ __half2 g_Qw[WV * 32];    // word buckets, fp16
__device__ float   g_Qa[AV * 64];    // atom buckets, fp32
__device__ float   g_Msum[NG * DD];
__device__ float   g_usum[2 * NG];   // [0..63]=u1=PÂ1, [64..127]=u2=PÂ²1
__device__ int     g_gcnt[NG];
__device__ float   g_T1[NG * DD];
__device__ float   g_T2[NG * DD];

// ---------------- CSR build (reverse: by src) --------------------------------

__global__ void hist_kernel(const int* __restrict__ ei) {
    int e = blockIdx.x * blockDim.x + threadIdx.x;
    if (e >= NE) return;
    atomicAdd(&g_cnt[ei[e]], 1);        // src -> rowptr
    atomicAdd(&g_cnt2[ei[NE + e]], 1);  // dst -> degree norm
}

__global__ void scan1_kernel() {
    __shared__ int sh[1024];
    int i = blockIdx.x * 1024 + threadIdx.x;
    int c = 0;
    if (i < NN) {
        c = g_cnt[i];
        int cd = g_cnt2[i];
        g_dinv[i]  = rsqrtf((float)(cd + 1));   // +1 self loop
        g_rdinv[i] = sqrtf((float)(cd + 1));
    }
    sh[threadIdx.x] = c;
    __syncthreads();
    for (int off = 512; off > 0; off >>= 1) {
        if (threadIdx.x < off) sh[threadIdx.x] += sh[threadIdx.x + off];
        __syncthreads();
    }
    if (threadIdx.x == 0) g_bsum[blockIdx.x] = sh[0];
}

__global__ void scan2_kernel() {
    __shared__ int sh[NB];
    int tid = threadIdx.x;
    if (tid < NB) sh[tid] = g_bsum[tid];
    __syncthreads();
    if (tid == 0) {
        int run = 0;
        for (int b = 0; b < NB; ++b) { g_boff[b] = run; run += sh[b]; }
        g_rowptr[NN] = run;   // == NE
    }
    for (int i = tid; i < NG * DD; i += blockDim.x) g_Msum[i] = 0.f;
    if (tid < 2 * NG) g_usum[tid] = 0.f;
    if (tid < NG)     g_gcnt[tid] = 0;
}

__global__ void scan3_kernel() {
    __shared__ int sh[1024];
    int tid = threadIdx.x;
    int i = blockIdx.x * 1024 + tid;
    int c = (i < NN) ? g_cnt[i] : 0;
    sh[tid] = c;
    __syncthreads();
    for (int off = 1; off < 1024; off <<= 1) {
        int v = (tid >= off) ? sh[tid - off] : 0;
        __syncthreads();
        sh[tid] += v;
        __syncthreads();
    }
    if (i < NN) {
        int excl = g_boff[blockIdx.x] + sh[tid] - c;
        g_rowptr[i] = excl;
        g_wpos[i]   = excl;
        g_cnt[i]    = 0;
        g_cnt2[i]   = 0;
    }
}

// fused: edge scatter + q0 init (z0 = dinv * one-hot(batch)) + gcnt + zero Qw/Qa
#define EDGE_BLOCKS ((NE + 255) / 256)
#define Q0_BLOCKS   ((NN * 8 + 255) / 256)
#define ZQW 80000                      // Qw uint4 count (10000*64*2/16)
#define ZQA 656                        // Qa uint4 count (41*64*4/16)
#define ZQ_BLOCKS   ((ZQW + ZQA + 255) / 256)
__global__ void scatter_init_kernel(const int* __restrict__ ei,
                                    const int* __restrict__ batch) {
    int b = blockIdx.x;
    if (b < EDGE_BLOCKS) {
        int e = b * 256 + threadIdx.x;
        if (e >= NE) return;
        int src = ei[e];
        int dst = ei[NE + e];
        int pos = atomicAdd(&g_wpos[src], 1);
        g_off[pos] = dst * 128;
    } else if (b < EDGE_BLOCKS + Q0_BLOCKS) {
        int idx = (b - EDGE_BLOCKS) * 256 + threadIdx.x;
        if (idx >= NN * 8) return;
        int i = idx >> 3, sub = idx & 7;
        int bg = batch[i];
        union { uint4 v; __half h[8]; } u;
        u.v = make_uint4(0, 0, 0, 0);
        int rel = bg - sub * 8;
        if (rel >= 0 && rel < 8) u.h[rel] = __float2half(g_dinv[i]);
        ((uint4*)g_hA)[i * 8 + sub] = u.v;
        if (sub == 0) atomicAdd(&g_gcnt[bg], 1);
    } else {
        int idx = (b - EDGE_BLOCKS - Q0_BLOCKS) * 256 + threadIdx.x;
        uint4 z = make_uint4(0, 0, 0, 0);
        if (idx < ZQW) ((uint4*)g_Qw)[idx] = z;
        else if (idx < ZQW + ZQA) ((uint4*)g_Qa)[idx - ZQW] = z;
    }
}

// one hop of q through A^T on pre-scaled rows (z = dinv .* q), 64-wide fp16.
// warp per node; 4 edges per iteration via 8-lane groups + shuffle reduce.
// last=0: out = dinv^2 * (sum + self)   (z for next hop)
// last=1: out = dinv   * (sum + self)   (true q3)
__global__ void hop_kernel(const __half2* __restrict__ in,
                           __half2* __restrict__ out, int last) {
    int i = blockIdx.x * 4 + (threadIdx.x >> 5);
    int lane = threadIdx.x & 31;
    int grp = lane >> 3, sub = lane & 7;
    int beg = g_rowptr[i], end = g_rowptr[i + 1];
    const char* base = (const char*)in + sub * 16;
    __half2 a0 = __float2half2_rn(0.f), a1 = a0, a2 = a0, a3 = a0;
    int n4 = (end - beg) & ~3;
    for (int k = 0; k < n4; k += 4) {
        int o = g_off[beg + k + grp];
        uint4 v = *(const uint4*)(base + o);
        a0 = __hadd2(a0, *(const __half2*)&v.x);
        a1 = __hadd2(a1, *(const __half2*)&v.y);
        a2 = __hadd2(a2, *(const __half2*)&v.z);
        a3 = __hadd2(a3, *(const __half2*)&v.w);
    }
    int r = beg + n4 + grp;
    if (r < end) {
        int o = g_off[r];
        uint4 v = *(const uint4*)(base + o);
        a0 = __hadd2(a0, *(const __half2*)&v.x);
        a1 = __hadd2(a1, *(const __half2*)&v.y);
        a2 = __hadd2(a2, *(const __half2*)&v.z);
        a3 = __hadd2(a3, *(const __half2*)&v.w);
    }
    // reduce the 4 lane-groups (lane, lane+8, lane+16, lane+24)
    a0 = __hadd2(a0, __shfl_down_sync(0xffffffffu, a0, 16));
    a1 = __hadd2(a1, __shfl_down_sync(0xffffffffu, a1, 16));
    a2 = __hadd2(a2, __shfl_down_sync(0xffffffffu, a2, 16));
    a3 = __hadd2(a3, __shfl_down_sync(0xffffffffu, a3, 16));
    a0 = __hadd2(a0, __shfl_down_sync(0xffffffffu, a0, 8));
    a1 = __hadd2(a1, __shfl_down_sync(0xffffffffu, a1, 8));
    a2 = __hadd2(a2, __shfl_down_sync(0xffffffffu, a2, 8));
    a3 = __hadd2(a3, __shfl_down_sync(0xffffffffu, a3, 8));
    if (lane < 8) {
        uint4 sv = *(const uint4*)(base + i * 128);
        float di = g_dinv[i];
        float f = last ? di : di * di;
        float2 s0 = __half22float2(*(__half2*)&sv.x);
        float2 s1 = __half22float2(*(__half2*)&sv.y);
        float2 s2 = __half22float2(*(__half2*)&sv.z);
        float2 s3 = __half22float2(*(__half2*)&sv.w);
        float2 f0 = __half22float2(a0), f1 = __half22float2(a1);
        float2 f2 = __half22float2(a2), f3 = __half22float2(a3);
        uint4 o;
        *(__half2*)&o.x = __float22half2_rn(make_float2(f*(f0.x+s0.x), f*(f0.y+s0.y)));
        *(__half2*)&o.y = __float22half2_rn(make_float2(f*(f1.x+s1.x), f*(f1.y+s1.y)));
        *(__half2*)&o.z = __float22half2_rn(make_float2(f*(f2.x+s2.x), f*(f2.y+s2.y)));
        *(__half2*)&o.w = __float22half2_rn(make_float2(f*(f3.x+s3.x), f*(f3.y+s3.y)));
        *(uint4*)((char*)out + i * 128 + sub * 16) = o;
    }
}

// column sums of true q = z * rdinv: u[g] = sum_i z[i][g] * rdinv[i]
#define CS_ROWS 500
__global__ void colsum_kernel(const __half2* __restrict__ z, float* __restrict__ u) {
    __shared__ float sm[8][64];
    int gp = threadIdx.x & 31, rg = threadIdx.x >> 5;
    int i0 = blockIdx.x * CS_ROWS;
    int i1 = i0 + CS_ROWS; if (i1 > NN) i1 = NN;
    float2 acc = make_float2(0.f, 0.f);
    for (int i = i0 + rg; i < i1; i += 8) {
        float2 v = __half22float2(z[(size_t)i * 32 + gp]);
        float rd = g_rdinv[i];
        acc.x += v.x * rd; acc.y += v.y * rd;
    }
    sm[rg][2 * gp] = acc.x; sm[rg][2 * gp + 1] = acc.y;
    __syncthreads();
    if (rg == 0) {
        float s0 = 0.f, s1 = 0.f;
        #pragma unroll
        for (int r2 = 0; r2 < 8; ++r2) { s0 += sm[r2][2 * gp]; s1 += sm[r2][2 * gp + 1]; }
        atomicAdd(&u[2 * gp], s0);
        atomicAdd(&u[2 * gp + 1], s1);
    }
}

// scatter q3 into vocab buckets: Qw[w][g] += q3[i][g], Qa[a][g] += q3[i][g]
#define VCH 512
__global__ void vscatter_kernel(const __half2* __restrict__ q3,
                                const int* __restrict__ x) {
    __shared__ float sQa[AV * 64];
    for (int k = threadIdx.x; k < AV * 64; k += 256) sQa[k] = 0.f;
    __syncthreads();
    int gp = threadIdx.x & 31, ns = threadIdx.x >> 5;
    int i0 = blockIdx.x * VCH;
    int i1 = i0 + VCH; if (i1 > NN) i1 = NN;
    for (int i = i0 + ns; i < i1; i += 8) {
        __half2 q = q3[(size_t)i * 32 + gp];
        int a = x[2 * i], w = x[2 * i + 1];
        atomicAdd(&g_Qw[w * 32 + gp], q);            // fp16x2 red, low contention
        float2 f = __half22float2(q);
        atomicAdd(&sQa[a * 64 + 2 * gp],     f.x);   // smem, high contention ok
        atomicAdd(&sQa[a * 64 + 2 * gp + 1], f.y);
    }
    __syncthreads();
    for (int k = threadIdx.x; k < AV * 64; k += 256) atomicAdd(&g_Qa[k], sQa[k]);
}

// Msum = Qw @ wt + Qa @ at   (64 x 300, K = 10000 / 41)
#define WPB 63
__global__ void vgemm_kernel(const float* __restrict__ wt,
                             const float* __restrict__ at) {
    __shared__ float qs[64];
    int d = threadIdx.x;   // 0..319, active < 300
    float acc[64];
    #pragma unroll
    for (int g = 0; g < 64; ++g) acc[g] = 0.f;
    if (blockIdx.x < 160) {
        int w0 = blockIdx.x * WPB;
        int w1 = w0 + WPB; if (w1 > WV) w1 = WV;
        for (int w = w0; w < w1; ++w) {
            __syncthreads();
            if (threadIdx.x < 32) {
                float2 f = __half22float2(g_Qw[w * 32 + threadIdx.x]);
                qs[2 * threadIdx.x] = f.x; qs[2 * threadIdx.x + 1] = f.y;
            }
            __syncthreads();
            if (d < DD) {
                float hv = wt[w * DD + d];
                #pragma unroll
                for (int g = 0; g < 64; ++g) acc[g] += qs[g] * hv;
            }
        }
    } else {
        for (int a = 0; a < AV; ++a) {
            __syncthreads();
            if (threadIdx.x < 64) qs[threadIdx.x] = g_Qa[a * 64 + threadIdx.x];
            __syncthreads();
            if (d < DD) {
                float hv = at[a * DD + d];
                #pragma unroll
                for (int g = 0; g < 64; ++g) acc[g] += qs[g] * hv;
            }
        }
    }
    if (d < DD) {
        #pragma unroll
        for (int g = 0; g < 64; ++g) atomicAdd(&g_Msum[g * DD + d], acc[g]);
    }
}

// epilogue GEMM step: out[g] = in[g]@W + coef[g]*b          (finalize=0)
//                     out[g] = in[g]@W/max(cnt,1)+(cnt>0)*b (finalize=1)
__global__ void mg_kernel(const float* __restrict__ in, float* __restrict__ outp,
                          const float* __restrict__ W, const float* __restrict__ bvec,
                          const float* __restrict__ coef, int finalize) {
    int g = blockIdx.x;
    int c = threadIdx.x;
    __shared__ float arow[DD];
    for (int k = c; k < DD; k += 320) arow[k] = in[g * DD + k];
    __syncthreads();
    if (c >= DD) return;
    float acc = 0.f;
    #pragma unroll 4
    for (int k = 0; k < DD; ++k) acc += arow[k] * W[k * DD + c];
    if (!finalize) {
        outp[g * DD + c] = acc + coef[g] * bvec[c];
    } else {
        int cnt = g_gcnt[g];
        float denom = (cnt > 0) ? (float)cnt : 1.f;
        float r = acc / denom;
        if (cnt > 0) r += bvec[c];
        outp[g * DD + c] = r;
    }
}

// ---------------- launch ----------------------------------------------------

extern "C" void kernel_launch(void* const* d_in, const int* in_sizes, int n_in,
                              void* d_out, int out_size) {
    const int*   x     = (const int*)d_in[0];     // [N,2]
    const int*   ei    = (const int*)d_in[1];     // [2,E]
    const int*   batch = (const int*)d_in[2];     // [N]
    const float* at    = (const float*)d_in[3];   // [41,300]
    const float* wt    = (const float*)d_in[4];   // [10000,300]
    const float* W     = (const float*)d_in[5];   // [300,300]
    const float* b     = (const float*)d_in[6];   // [300]
    float* out = (float*)d_out;

    __half2 *hA, *hB;
    float *T1, *T2, *Msum, *usum;
    cudaGetSymbolAddress((void**)&hA,   g_hA);
    cudaGetSymbolAddress((void**)&hB,   g_hB);
    cudaGetSymbolAddress((void**)&T1,   g_T1);
    cudaGetSymbolAddress((void**)&T2,   g_T2);
    cudaGetSymbolAddress((void**)&Msum, g_Msum);
    cudaGetSymbolAddress((void**)&usum, g_usum);

    // reverse-CSR build (by src); dinv from dst in-degree
    hist_kernel<<<(NE + 255) / 256, 256>>>(ei);                              // 0
    scan1_kernel<<<NB, 1024>>>();                                            // 1
    scan2_kernel<<<1, 256>>>();                                              // 2
    scan3_kernel<<<NB, 1024>>>();                                            // 3
    scatter_init_kernel<<<EDGE_BLOCKS + Q0_BLOCKS + ZQ_BLOCKS, 256>>>(ei, batch); // 4
    // q-hops: z0 -> z1 -> z2 -> q3 (column sums give u1 = PÂ1, u2 = PÂ²1)
    hop_kernel<<<NN / 4, 128>>>(hA, hB, 0);                                  // 5
    colsum_kernel<<<(NN + CS_ROWS - 1) / CS_ROWS, 256>>>(hB, usum);          // 6
    hop_kernel<<<NN / 4, 128>>>(hB, hA, 0);                                  // 7
    colsum_kernel<<<(NN + CS_ROWS - 1) / CS_ROWS, 256>>>(hA, usum + NG);     // 8
    hop_kernel<<<NN / 4, 128>>>(hA, hB, 1);                                  // 9 -> q3 in hB
    // factor through embedding tables: Msum = q3^T Ia at + q3^T Iw wt
    vscatter_kernel<<<(NN + VCH - 1) / VCH, 256>>>(hB, x);                   // 10
    vgemm_kernel<<<161, 320>>>(wt, at);                                      // 11
    // epilogue: ((Msum@W + u2⊗b)@W + u1⊗b)@W, then /cnt + b
    mg_kernel<<<NG, 320>>>(Msum, T1, W, b, usum + NG, 0);                    // 12
    mg_kernel<<<NG, 320>>>(T1,   T2, W, b, usum,      0);                    // 13
    mg_kernel<<<NG, 320>>>(T2,  out, W, b, usum,      1);                    // 14
}

// round 15
// speedup vs baseline: 1.0010x; 1.0003x over previous
#include <cuda_runtime.h>
#include <cuda_fp16.h>

#define NN 100000
#define NE 800000
#define DD 300
#define NG 64
#define NB 98            // scan blocks (98 * 1024 >= NN)
#define WV 10000         // word vocab
#define AV 41            // atom vocab

// ---------------- scratch (device globals; no allocation allowed) ----------
__device__ int     g_cnt[NN];        // src counts (rowptr);  self-reset in scan3
__device__ int     g_cnt2[NN];       // dst counts (dinv);    self-reset in scan3
__device__ int     g_rowptr[NN + 1];
__device__ int     g_wpos[NN];
__device__ int     g_off[NE];        // byte offset of gathered row (dst*128)
__device__ float   g_dinv[NN];
__device__ float   g_rdinv[NN];
__device__ int     g_bsum[NB];
__device__ int     g_boff[NB];
__device__ __half2 g_hA[(size_t)NN * 32];   // 12.8 MB (q rows, 64 fp16)
__device__ __half2 g_hB[(size_t)NN * 32];   // 12.8 MB
__device__ __half2 g_Qw[WV * 32];    // word buckets, fp16
__device__ float   g_Qa[AV * 64];    // atom buckets, fp32
__device__ float   g_Msum[NG * DD];
__device__ float   g_usum[2 * NG];   // [0..63]=u1=PÂ1, [64..127]=u2=PÂ²1
__device__ int     g_gcnt[NG];
__device__ float   g_T1[NG * DD];
__device__ float   g_T2[NG * DD];

// ---------------- CSR build (reverse: by src) --------------------------------

__global__ void hist_kernel(const int* __restrict__ ei) {
    int e = blockIdx.x * blockDim.x + threadIdx.x;
    if (e >= NE) return;
    atomicAdd(&g_cnt[ei[e]], 1);        // src -> rowptr
    atomicAdd(&g_cnt2[ei[NE + e]], 1);  // dst -> degree norm
}

__global__ void scan1_kernel() {
    __shared__ int sh[1024];
    int i = blockIdx.x * 1024 + threadIdx.x;
    int c = 0;
    if (i < NN) {
        c = g_cnt[i];
        int cd = g_cnt2[i];
        g_dinv[i]  = rsqrtf((float)(cd + 1));   // +1 self loop
        g_rdinv[i] = sqrtf((float)(cd + 1));
    }
    sh[threadIdx.x] = c;
    __syncthreads();
    for (int off = 512; off > 0; off >>= 1) {
        if (threadIdx.x < off) sh[threadIdx.x] += sh[threadIdx.x + off];
        __syncthreads();
    }
    if (threadIdx.x == 0) g_bsum[blockIdx.x] = sh[0];
}

__global__ void scan2_kernel() {
    __shared__ int sh[NB];
    int tid = threadIdx.x;
    if (tid < NB) sh[tid] = g_bsum[tid];
    __syncthreads();
    if (tid == 0) {
        int run = 0;
        for (int b = 0; b < NB; ++b) { g_boff[b] = run; run += sh[b]; }
        g_rowptr[NN] = run;   // == NE
    }
    for (int i = tid; i < NG * DD; i += blockDim.x) g_Msum[i] = 0.f;
    if (tid < 2 * NG) g_usum[tid] = 0.f;
    if (tid < NG)     g_gcnt[tid] = 0;
}

__global__ void scan3_kernel() {
    __shared__ int sh[1024];
    int tid = threadIdx.x;
    int i = blockIdx.x * 1024 + tid;
    int c = (i < NN) ? g_cnt[i] : 0;
    sh[tid] = c;
    __syncthreads();
    for (int off = 1; off < 1024; off <<= 1) {
        int v = (tid >= off) ? sh[tid - off] : 0;
        __syncthreads();
        sh[tid] += v;
        __syncthreads();
    }
    if (i < NN) {
        int excl = g_boff[blockIdx.x] + sh[tid] - c;
        g_rowptr[i] = excl;
        g_wpos[i]   = excl;
        g_cnt[i]    = 0;
        g_cnt2[i]   = 0;
    }
}

// fused: edge scatter + q0 init (z0 = dinv * one-hot(batch)) + gcnt + zero Qw/Qa
#define EDGE_BLOCKS ((NE + 255) / 256)
#define Q0_BLOCKS   ((NN * 8 + 255) / 256)
#define ZQW 80000                      // Qw uint4 count (10000*64*2/16)
#define ZQA 656                        // Qa uint4 count (41*64*4/16)
#define ZQ_BLOCKS   ((ZQW + ZQA + 255) / 256)
__global__ void scatter_init_kernel(const int* __restrict__ ei,
                                    const int* __restrict__ batch) {
    int b = blockIdx.x;
    if (b < EDGE_BLOCKS) {
        int e = b * 256 + threadIdx.x;
        if (e >= NE) return;
        int src = ei[e];
        int dst = ei[NE + e];
        int pos = atomicAdd(&g_wpos[src], 1);
        g_off[pos] = dst * 128;
    } else if (b < EDGE_BLOCKS + Q0_BLOCKS) {
        int idx = (b - EDGE_BLOCKS) * 256 + threadIdx.x;
        if (idx >= NN * 8) return;
        int i = idx >> 3, sub = idx & 7;
        int bg = batch[i];
        union { uint4 v; __half h[8]; } u;
        u.v = make_uint4(0, 0, 0, 0);
        int rel = bg - sub * 8;
        if (rel >= 0 && rel < 8) u.h[rel] = __float2half(g_dinv[i]);
        ((uint4*)g_hA)[i * 8 + sub] = u.v;
        if (sub == 0) atomicAdd(&g_gcnt[bg], 1);
    } else {
        int idx = (b - EDGE_BLOCKS - Q0_BLOCKS) * 256 + threadIdx.x;
        uint4 z = make_uint4(0, 0, 0, 0);
        if (idx < ZQW) ((uint4*)g_Qw)[idx] = z;
        else if (idx < ZQW + ZQA) ((uint4*)g_Qa)[idx - ZQW] = z;
    }
}

// one hop of q through A^T on pre-scaled rows (z = dinv .* q), 64-wide fp16.
// warp per node; 4 edges per iteration via 8-lane groups + shuffle reduce.
// last=0: out = dinv^2 * (sum + self)   (z for next hop)
// last=1: out = dinv   * (sum + self)   (true q3)
__global__ void hop_kernel(const __half2* __restrict__ in,
                           __half2* __restrict__ out, int last) {
    int i = blockIdx.x * 4 + (threadIdx.x >> 5);
    int lane = threadIdx.x & 31;
    int grp = lane >> 3, sub = lane & 7;
    int beg = g_rowptr[i], end = g_rowptr[i + 1];
    const char* base = (const char*)in + sub * 16;
    __half2 a0 = __float2half2_rn(0.f), a1 = a0, a2 = a0, a3 = a0;
    int n4 = (end - beg) & ~3;
    for (int k = 0; k < n4; k += 4) {
        int o = g_off[beg + k + grp];
        uint4 v = *(const uint4*)(base + o);
        a0 = __hadd2(a0, *(const __half2*)&v.x);
        a1 = __hadd2(a1, *(const __half2*)&v.y);
        a2 = __hadd2(a2, *(const __half2*)&v.z);
        a3 = __hadd2(a3, *(const __half2*)&v.w);
    }
    int r = beg + n4 + grp;
    if (r < end) {
        int o = g_off[r];
        uint4 v = *(const uint4*)(base + o);
        a0 = __hadd2(a0, *(const __half2*)&v.x);
        a1 = __hadd2(a1, *(const __half2*)&v.y);
        a2 = __hadd2(a2, *(const __half2*)&v.z);
        a3 = __hadd2(a3, *(const __half2*)&v.w);
    }
    // reduce the 4 lane-groups (lane, lane+8, lane+16, lane+24)
    a0 = __hadd2(a0, __shfl_down_sync(0xffffffffu, a0, 16));
    a1 = __hadd2(a1, __shfl_down_sync(0xffffffffu, a1, 16));
    a2 = __hadd2(a2, __shfl_down_sync(0xffffffffu, a2, 16));
    a3 = __hadd2(a3, __shfl_down_sync(0xffffffffu, a3, 16));
    a0 = __hadd2(a0, __shfl_down_sync(0xffffffffu, a0, 8));
    a1 = __hadd2(a1, __shfl_down_sync(0xffffffffu, a1, 8));
    a2 = __hadd2(a2, __shfl_down_sync(0xffffffffu, a2, 8));
    a3 = __hadd2(a3, __shfl_down_sync(0xffffffffu, a3, 8));
    if (lane < 8) {
        uint4 sv = *(const uint4*)(base + i * 128);
        float di = g_dinv[i];
        float f = last ? di : di * di;
        float2 s0 = __half22float2(*(__half2*)&sv.x);
        float2 s1 = __half22float2(*(__half2*)&sv.y);
        float2 s2 = __half22float2(*(__half2*)&sv.z);
        float2 s3 = __half22float2(*(__half2*)&sv.w);
        float2 f0 = __half22float2(a0), f1 = __half22float2(a1);
        float2 f2 = __half22float2(a2), f3 = __half22float2(a3);
        uint4 o;
        *(__half2*)&o.x = __float22half2_rn(make_float2(f*(f0.x+s0.x), f*(f0.y+s0.y)));
        *(__half2*)&o.y = __float22half2_rn(make_float2(f*(f1.x+s1.x), f*(f1.y+s1.y)));
        *(__half2*)&o.z = __float22half2_rn(make_float2(f*(f2.x+s2.x), f*(f2.y+s2.y)));
        *(__half2*)&o.w = __float22half2_rn(make_float2(f*(f3.x+s3.x), f*(f3.y+s3.y)));
        *(uint4*)((char*)out + i * 128 + sub * 16) = o;
    }
}

// column sums of true q = z * rdinv: u[g] = sum_i z[i][g] * rdinv[i]
#define CS_ROWS 500
__global__ void colsum_kernel(const __half2* __restrict__ z, float* __restrict__ u) {
    __shared__ float sm[8][64];
    int gp = threadIdx.x & 31, rg = threadIdx.x >> 5;
    int i0 = blockIdx.x * CS_ROWS;
    int i1 = i0 + CS_ROWS; if (i1 > NN) i1 = NN;
    float2 acc = make_float2(0.f, 0.f);
    for (int i = i0 + rg; i < i1; i += 8) {
        float2 v = __half22float2(z[(size_t)i * 32 + gp]);
        float rd = g_rdinv[i];
        acc.x += v.x * rd; acc.y += v.y * rd;
    }
    sm[rg][2 * gp] = acc.x; sm[rg][2 * gp + 1] = acc.y;
    __syncthreads();
    if (rg == 0) {
        float s0 = 0.f, s1 = 0.f;
        #pragma unroll
        for (int r2 = 0; r2 < 8; ++r2) { s0 += sm[r2][2 * gp]; s1 += sm[r2][2 * gp + 1]; }
        atomicAdd(&u[2 * gp], s0);
        atomicAdd(&u[2 * gp + 1], s1);
    }
}

// scatter q3 into vocab buckets: Qw[w][g] += q3[i][g], Qa[a][g] += q3[i][g]
#define VCH 512
__global__ void vscatter_kernel(const __half2* __restrict__ q3,
                                const int* __restrict__ x) {
    __shared__ float sQa[AV * 64];
    for (int k = threadIdx.x; k < AV * 64; k += 256) sQa[k] = 0.f;
    __syncthreads();
    int gp = threadIdx.x & 31, ns = threadIdx.x >> 5;
    int i0 = blockIdx.x * VCH;
    int i1 = i0 + VCH; if (i1 > NN) i1 = NN;
    for (int i = i0 + ns; i < i1; i += 8) {
        __half2 q = q3[(size_t)i * 32 + gp];
        int a = x[2 * i], w = x[2 * i + 1];
        atomicAdd(&g_Qw[w * 32 + gp], q);            // fp16x2 red, low contention
        float2 f = __half22float2(q);
        atomicAdd(&sQa[a * 64 + 2 * gp],     f.x);   // smem, high contention ok
        atomicAdd(&sQa[a * 64 + 2 * gp + 1], f.y);
    }
    __syncthreads();
    for (int k = threadIdx.x; k < AV * 64; k += 256) atomicAdd(&g_Qa[k], sQa[k]);
}

// Msum = Qw @ wt + Qa @ at   (64 x 300, K = 10000 / 41)
#define WPB 63
__global__ void vgemm_kernel(const float* __restrict__ wt,
                             const float* __restrict__ at) {
    __shared__ float qs[64];
    int d = threadIdx.x;   // 0..319, active < 300
    float acc[64];
    #pragma unroll
    for (int g = 0; g < 64; ++g) acc[g] = 0.f;
    if (blockIdx.x < 160) {
        int w0 = blockIdx.x * WPB;
        int w1 = w0 + WPB; if (w1 > WV) w1 = WV;
        for (int w = w0; w < w1; ++w) {
            __syncthreads();
            if (threadIdx.x < 32) {
                float2 f = __half22float2(g_Qw[w * 32 + threadIdx.x]);
                qs[2 * threadIdx.x] = f.x; qs[2 * threadIdx.x + 1] = f.y;
            }
            __syncthreads();
            if (d < DD) {
                float hv = wt[w * DD + d];
                #pragma unroll
                for (int g = 0; g < 64; ++g) acc[g] += qs[g] * hv;
            }
        }
    } else {
        for (int a = 0; a < AV; ++a) {
            __syncthreads();
            if (threadIdx.x < 64) qs[threadIdx.x] = g_Qa[a * 64 + threadIdx.x];
            __syncthreads();
            if (d < DD) {
                float hv = at[a * DD + d];
                #pragma unroll
                for (int g = 0; g < 64; ++g) acc[g] += qs[g] * hv;
            }
        }
    }
    if (d < DD) {
        #pragma unroll
        for (int g = 0; g < 64; ++g) atomicAdd(&g_Msum[g * DD + d], acc[g]);
    }
}

// epilogue GEMM step: out[g] = in[g]@W + coef[g]*b          (finalize=0)
//                     out[g] = in[g]@W/max(cnt,1)+(cnt>0)*b (finalize=1)
__global__ void mg_kernel(const float* __restrict__ in, float* __restrict__ outp,
                          const float* __restrict__ W, const float* __restrict__ bvec,
                          const float* __restrict__ coef, int finalize) {
    int g = blockIdx.x;
    int c = threadIdx.x;
    __shared__ float arow[DD];
    for (int k = c; k < DD; k += 320) arow[k] = in[g * DD + k];
    __syncthreads();
    if (c >= DD) return;
    float acc = 0.f;
    #pragma unroll 4
    for (int k = 0; k < DD; ++k) acc += arow[k] * W[k * DD + c];
    if (!finalize) {
        outp[g * DD + c] = acc + coef[g] * bvec[c];
    } else {
        int cnt = g_gcnt[g];
        float denom = (cnt > 0) ? (float)cnt : 1.f;
        float r = acc / denom;
        if (cnt > 0) r += bvec[c];
        outp[g * DD + c] = r;
    }
}

// ---------------- launch ----------------------------------------------------

extern "C" void kernel_launch(void* const* d_in, const int* in_sizes, int n_in,
                              void* d_out, int out_size) {
    const int*   x     = (const int*)d_in[0];     // [N,2]
    const int*   ei    = (const int*)d_in[1];     // [2,E]
    const int*   batch = (const int*)d_in[2];     // [N]
    const float* at    = (const float*)d_in[3];   // [41,300]
    const float* wt    = (const float*)d_in[4];   // [10000,300]
    const float* W     = (const float*)d_in[5];   // [300,300]
    const float* b     = (const float*)d_in[6];   // [300]
    float* out = (float*)d_out;

    __half2 *hA, *hB;
    float *T1, *T2, *Msum, *usum;
    cudaGetSymbolAddress((void**)&hA,   g_hA);
    cudaGetSymbolAddress((void**)&hB,   g_hB);
    cudaGetSymbolAddress((void**)&T1,   g_T1);
    cudaGetSymbolAddress((void**)&T2,   g_T2);
    cudaGetSymbolAddress((void**)&Msum, g_Msum);
    cudaGetSymbolAddress((void**)&usum, g_usum);

    // reverse-CSR build (by src); dinv from dst in-degree
    hist_kernel<<<(NE + 255) / 256, 256>>>(ei);                              // 0
    scan1_kernel<<<NB, 1024>>>();                                            // 1
    scan2_kernel<<<1, 256>>>();                                              // 2
    scan3_kernel<<<NB, 1024>>>();                                            // 3
    scatter_init_kernel<<<EDGE_BLOCKS + Q0_BLOCKS + ZQ_BLOCKS, 256>>>(ei, batch); // 4
    // q-hops: z0 -> z1 -> z2 -> q3 (column sums give u1 = PÂ1, u2 = PÂ²1)
    hop_kernel<<<NN / 4, 128>>>(hA, hB, 0);                                  // 5
    colsum_kernel<<<(NN + CS_ROWS - 1) / CS_ROWS, 256>>>(hB, usum);          // 6
    hop_kernel<<<NN / 4, 128>>>(hB, hA, 0);                                  // 7
    colsum_kernel<<<(NN + CS_ROWS - 1) / CS_ROWS, 256>>>(hA, usum + NG);     // 8
    hop_kernel<<<NN / 4, 128>>>(hA, hB, 1);                                  // 9 -> q3 in hB
    // factor through embedding tables: Msum = q3^T Ia at + q3^T Iw wt
    vscatter_kernel<<<(NN + VCH - 1) / VCH, 256>>>(hB, x);                   // 10
    vgemm_kernel<<<161, 320>>>(wt, at);                                      // 11
    // epilogue: ((Msum@W + u2⊗b)@W + u1⊗b)@W, then /cnt + b
    mg_kernel<<<NG, 320>>>(Msum, T1, W, b, usum + NG, 0);                    // 12
    mg_kernel<<<NG, 320>>>(T1,   T2, W, b, usum,      0);                    // 13
    mg_kernel<<<NG, 320>>>(T2,  out, W, b, usum,      1);                    // 14
}

// round 16
// speedup vs baseline: 1.0033x; 1.0022x over previous
#include <cuda_runtime.h>
#include <cuda_fp16.h>

#define NN 100000
#define NE 800000
#define DD 300
#define NG 64
#define NB 98            // scan blocks (98 * 1024 >= NN)
#define WV 10000         // word vocab
#define AV 41            // atom vocab

// ---------------- scratch (device globals; no allocation allowed) ----------
__device__ int     g_cnt[NN];        // src counts (rowptr);  self-reset in scan3
__device__ int     g_cnt2[NN];       // dst counts (dinv);    self-reset in scan3
__device__ int     g_rowptr[NN + 1];
__device__ int     g_wpos[NN];
__device__ int     g_off[NE];        // byte offset of gathered row (dst*128)
__device__ float   g_dinv[NN];
__device__ float   g_rdinv[NN];
__device__ int     g_bsum[NB];
__device__ int     g_boff[NB];
__device__ __half2 g_hA[(size_t)NN * 32];   // 12.8 MB (q rows, 64 fp16)
__device__ __half2 g_hB[(size_t)NN * 32];   // 12.8 MB
__device__ __half2 g_Qw[WV * 32];    // word buckets, fp16
__device__ float   g_Qa[AV * 64];    // atom buckets, fp32
__device__ float   g_Msum[NG * DD];
__device__ float   g_usum[2 * NG];   // [0..63]=u1=PÂ1, [64..127]=u2=PÂ²1
__device__ int     g_gcnt[NG];
__device__ float   g_T1[NG * DD];
__device__ float   g_T2[NG * DD];

// ---------------- CSR build (reverse: by src) --------------------------------

__global__ void hist_kernel(const int* __restrict__ ei) {
    int e = blockIdx.x * blockDim.x + threadIdx.x;
    if (e >= NE) return;
    atomicAdd(&g_cnt[ei[e]], 1);        // src -> rowptr
    atomicAdd(&g_cnt2[ei[NE + e]], 1);  // dst -> degree norm
}

__global__ void scan1_kernel() {
    __shared__ int sh[1024];
    int i = blockIdx.x * 1024 + threadIdx.x;
    int c = 0;
    if (i < NN) {
        c = g_cnt[i];
        int cd = g_cnt2[i];
        g_dinv[i]  = rsqrtf((float)(cd + 1));   // +1 self loop
        g_rdinv[i] = sqrtf((float)(cd + 1));
    }
    sh[threadIdx.x] = c;
    __syncthreads();
    for (int off = 512; off > 0; off >>= 1) {
        if (threadIdx.x < off) sh[threadIdx.x] += sh[threadIdx.x + off];
        __syncthreads();
    }
    if (threadIdx.x == 0) g_bsum[blockIdx.x] = sh[0];
}

__global__ void scan2_kernel() {
    __shared__ int sh[NB];
    int tid = threadIdx.x;
    if (tid < NB) sh[tid] = g_bsum[tid];
    __syncthreads();
    if (tid == 0) {
        int run = 0;
        for (int b = 0; b < NB; ++b) { g_boff[b] = run; run += sh[b]; }
        g_rowptr[NN] = run;   // == NE
    }
    for (int i = tid; i < NG * DD; i += blockDim.x) g_Msum[i] = 0.f;
    if (tid < 2 * NG) g_usum[tid] = 0.f;
    if (tid < NG)     g_gcnt[tid] = 0;
}

__global__ void scan3_kernel() {
    __shared__ int sh[1024];
    int tid = threadIdx.x;
    int i = blockIdx.x * 1024 + tid;
    int c = (i < NN) ? g_cnt[i] : 0;
    sh[tid] = c;
    __syncthreads();
    for (int off = 1; off < 1024; off <<= 1) {
        int v = (tid >= off) ? sh[tid - off] : 0;
        __syncthreads();
        sh[tid] += v;
        __syncthreads();
    }
    if (i < NN) {
        int excl = g_boff[blockIdx.x] + sh[tid] - c;
        g_rowptr[i] = excl;
        g_wpos[i]   = excl;
        g_cnt[i]    = 0;
        g_cnt2[i]   = 0;
    }
}

// fused: edge scatter + q0 init (z0 = dinv * one-hot(batch)) + gcnt + zero Qw/Qa
#define EDGE_BLOCKS ((NE + 255) / 256)
#define Q0_BLOCKS   ((NN * 8 + 255) / 256)
#define ZQW 80000                      // Qw uint4 count (10000*64*2/16)
#define ZQA 656                        // Qa uint4 count (41*64*4/16)
#define ZQ_BLOCKS   ((ZQW + ZQA + 255) / 256)
__global__ void scatter_init_kernel(const int* __restrict__ ei,
                                    const int* __restrict__ batch) {
    int b = blockIdx.x;
    if (b < EDGE_BLOCKS) {
        int e = b * 256 + threadIdx.x;
        if (e >= NE) return;
        int src = ei[e];
        int dst = ei[NE + e];
        int pos = atomicAdd(&g_wpos[src], 1);
        g_off[pos] = dst * 128;
    } else if (b < EDGE_BLOCKS + Q0_BLOCKS) {
        int idx = (b - EDGE_BLOCKS) * 256 + threadIdx.x;
        if (idx >= NN * 8) return;
        int i = idx >> 3, sub = idx & 7;
        int bg = batch[i];
        union { uint4 v; __half h[8]; } u;
        u.v = make_uint4(0, 0, 0, 0);
        int rel = bg - sub * 8;
        if (rel >= 0 && rel < 8) u.h[rel] = __float2half(g_dinv[i]);
        ((uint4*)g_hA)[i * 8 + sub] = u.v;
        if (sub == 0) atomicAdd(&g_gcnt[bg], 1);
    } else {
        int idx = (b - EDGE_BLOCKS - Q0_BLOCKS) * 256 + threadIdx.x;
        uint4 z = make_uint4(0, 0, 0, 0);
        if (idx < ZQW) ((uint4*)g_Qw)[idx] = z;
        else if (idx < ZQW + ZQA) ((uint4*)g_Qa)[idx - ZQW] = z;
    }
}

// one hop of q through A^T on pre-scaled rows (z = dinv .* q), 64-wide fp16.
// warp per node; 4 edges per iteration via 8-lane groups + shuffle reduce.
// last=0: out = dinv^2 * (sum + self)   (z for next hop)
// last=1: out = dinv   * (sum + self)   (true q3)
__global__ void hop_kernel(const __half2* __restrict__ in,
                           __half2* __restrict__ out, int last) {
    int i = blockIdx.x * 4 + (threadIdx.x >> 5);
    int lane = threadIdx.x & 31;
    int grp = lane >> 3, sub = lane & 7;
    int beg = g_rowptr[i], end = g_rowptr[i + 1];
    const char* base = (const char*)in + sub * 16;
    __half2 a0 = __float2half2_rn(0.f), a1 = a0, a2 = a0, a3 = a0;
    int n4 = (end - beg) & ~3;
    for (int k = 0; k < n4; k += 4) {
        int o = g_off[beg + k + grp];
        uint4 v = *(const uint4*)(base + o);
        a0 = __hadd2(a0, *(const __half2*)&v.x);
        a1 = __hadd2(a1, *(const __half2*)&v.y);
        a2 = __hadd2(a2, *(const __half2*)&v.z);
        a3 = __hadd2(a3, *(const __half2*)&v.w);
    }
    int r = beg + n4 + grp;
    if (r < end) {
        int o = g_off[r];
        uint4 v = *(const uint4*)(base + o);
        a0 = __hadd2(a0, *(const __half2*)&v.x);
        a1 = __hadd2(a1, *(const __half2*)&v.y);
        a2 = __hadd2(a2, *(const __half2*)&v.z);
        a3 = __hadd2(a3, *(const __half2*)&v.w);
    }
    // reduce the 4 lane-groups (lane, lane+8, lane+16, lane+24)
    a0 = __hadd2(a0, __shfl_down_sync(0xffffffffu, a0, 16));
    a1 = __hadd2(a1, __shfl_down_sync(0xffffffffu, a1, 16));
    a2 = __hadd2(a2, __shfl_down_sync(0xffffffffu, a2, 16));
    a3 = __hadd2(a3, __shfl_down_sync(0xffffffffu, a3, 16));
    a0 = __hadd2(a0, __shfl_down_sync(0xffffffffu, a0, 8));
    a1 = __hadd2(a1, __shfl_down_sync(0xffffffffu, a1, 8));
    a2 = __hadd2(a2, __shfl_down_sync(0xffffffffu, a2, 8));
    a3 = __hadd2(a3, __shfl_down_sync(0xffffffffu, a3, 8));
    if (lane < 8) {
        uint4 sv = *(const uint4*)(base + i * 128);
        float di = g_dinv[i];
        float f = last ? di : di * di;
        float2 s0 = __half22float2(*(__half2*)&sv.x);
        float2 s1 = __half22float2(*(__half2*)&sv.y);
        float2 s2 = __half22float2(*(__half2*)&sv.z);
        float2 s3 = __half22float2(*(__half2*)&sv.w);
        float2 f0 = __half22float2(a0), f1 = __half22float2(a1);
        float2 f2 = __half22float2(a2), f3 = __half22float2(a3);
        uint4 o;
        *(__half2*)&o.x = __float22half2_rn(make_float2(f*(f0.x+s0.x), f*(f0.y+s0.y)));
        *(__half2*)&o.y = __float22half2_rn(make_float2(f*(f1.x+s1.x), f*(f1.y+s1.y)));
        *(__half2*)&o.z = __float22half2_rn(make_float2(f*(f2.x+s2.x), f*(f2.y+s2.y)));
        *(__half2*)&o.w = __float22half2_rn(make_float2(f*(f3.x+s3.x), f*(f3.y+s3.y)));
        *(uint4*)((char*)out + i * 128 + sub * 16) = o;
    }
}

// column sums of true q = z * rdinv: u[g] = sum_i z[i][g] * rdinv[i]
#define CS_ROWS 500
__global__ void colsum_kernel(const __half2* __restrict__ z, float* __restrict__ u) {
    __shared__ float sm[8][64];
    int gp = threadIdx.x & 31, rg = threadIdx.x >> 5;
    int i0 = blockIdx.x * CS_ROWS;
    int i1 = i0 + CS_ROWS; if (i1 > NN) i1 = NN;
    float2 acc = make_float2(0.f, 0.f);
    for (int i = i0 + rg; i < i1; i += 8) {
        float2 v = __half22float2(z[(size_t)i * 32 + gp]);
        float rd = g_rdinv[i];
        acc.x += v.x * rd; acc.y += v.y * rd;
    }
    sm[rg][2 * gp] = acc.x; sm[rg][2 * gp + 1] = acc.y;
    __syncthreads();
    if (rg == 0) {
        float s0 = 0.f, s1 = 0.f;
        #pragma unroll
        for (int r2 = 0; r2 < 8; ++r2) { s0 += sm[r2][2 * gp]; s1 += sm[r2][2 * gp + 1]; }
        atomicAdd(&u[2 * gp], s0);
        atomicAdd(&u[2 * gp + 1], s1);
    }
}

// scatter q3 into vocab buckets: Qw[w][g] += q3[i][g], Qa[a][g] += q3[i][g]
#define VCH 512
__global__ void vscatter_kernel(const __half2* __restrict__ q3,
                                const int* __restrict__ x) {
    __shared__ float sQa[AV * 64];
    for (int k = threadIdx.x; k < AV * 64; k += 256) sQa[k] = 0.f;
    __syncthreads();
    int gp = threadIdx.x & 31, ns = threadIdx.x >> 5;
    int i0 = blockIdx.x * VCH;
    int i1 = i0 + VCH; if (i1 > NN) i1 = NN;
    for (int i = i0 + ns; i < i1; i += 8) {
        __half2 q = q3[(size_t)i * 32 + gp];
        int a = x[2 * i], w = x[2 * i + 1];
        atomicAdd(&g_Qw[w * 32 + gp], q);            // fp16x2 red, low contention
        float2 f = __half22float2(q);
        atomicAdd(&sQa[a * 64 + 2 * gp],     f.x);   // smem, high contention ok
        atomicAdd(&sQa[a * 64 + 2 * gp + 1], f.y);
    }
    __syncthreads();
    for (int k = threadIdx.x; k < AV * 64; k += 256) atomicAdd(&g_Qa[k], sQa[k]);
}

// Msum = Qw @ wt + Qa @ at   (64 x 300, K = 10000 / 41)
#define WPB 63
__global__ void vgemm_kernel(const float* __restrict__ wt,
                             const float* __restrict__ at) {
    __shared__ float qs[64];
    int d = threadIdx.x;   // 0..319, active < 300
    float acc[64];
    #pragma unroll
    for (int g = 0; g < 64; ++g) acc[g] = 0.f;
    if (blockIdx.x < 160) {
        int w0 = blockIdx.x * WPB;
        int w1 = w0 + WPB; if (w1 > WV) w1 = WV;
        for (int w = w0; w < w1; ++w) {
            __syncthreads();
            if (threadIdx.x < 32) {
                float2 f = __half22float2(g_Qw[w * 32 + threadIdx.x]);
                qs[2 * threadIdx.x] = f.x; qs[2 * threadIdx.x + 1] = f.y;
            }
            __syncthreads();
            if (d < DD) {
                float hv = wt[w * DD + d];
                #pragma unroll
                for (int g = 0; g < 64; ++g) acc[g] += qs[g] * hv;
            }
        }
    } else {
        for (int a = 0; a < AV; ++a) {
            __syncthreads();
            if (threadIdx.x < 64) qs[threadIdx.x] = g_Qa[a * 64 + threadIdx.x];
            __syncthreads();
            if (d < DD) {
                float hv = at[a * DD + d];
                #pragma unroll
                for (int g = 0; g < 64; ++g) acc[g] += qs[g] * hv;
            }
        }
    }
    if (d < DD) {
        #pragma unroll
        for (int g = 0; g < 64; ++g) atomicAdd(&g_Msum[g * DD + d], acc[g]);
    }
}

// epilogue GEMM step: out[g] = in[g]@W + coef[g]*b          (finalize=0)
//                     out[g] = in[g]@W/max(cnt,1)+(cnt>0)*b (finalize=1)
__global__ void mg_kernel(const float* __restrict__ in, float* __restrict__ outp,
                          const float* __restrict__ W, const float* __restrict__ bvec,
                          const float* __restrict__ coef, int finalize) {
    int g = blockIdx.x;
    int c = threadIdx.x;
    __shared__ float arow[DD];
    for (int k = c; k < DD; k += 320) arow[k] = in[g * DD + k];
    __syncthreads();
    if (c >= DD) return;
    float acc = 0.f;
    #pragma unroll 4
    for (int k = 0; k < DD; ++k) acc += arow[k] * W[k * DD + c];
    if (!finalize) {
        outp[g * DD + c] = acc + coef[g] * bvec[c];
    } else {
        int cnt = g_gcnt[g];
        float denom = (cnt > 0) ? (float)cnt : 1.f;
        float r = acc / denom;
        if (cnt > 0) r += bvec[c];
        outp[g * DD + c] = r;
    }
}

// ---------------- launch ----------------------------------------------------

extern "C" void kernel_launch(void* const* d_in, const int* in_sizes, int n_in,
                              void* d_out, int out_size) {
    const int*   x     = (const int*)d_in[0];     // [N,2]
    const int*   ei    = (const int*)d_in[1];     // [2,E]
    const int*   batch = (const int*)d_in[2];     // [N]
    const float* at    = (const float*)d_in[3];   // [41,300]
    const float* wt    = (const float*)d_in[4];   // [10000,300]
    const float* W     = (const float*)d_in[5];   // [300,300]
    const float* b     = (const float*)d_in[6];   // [300]
    float* out = (float*)d_out;

    __half2 *hA, *hB;
    float *T1, *T2, *Msum, *usum;
    cudaGetSymbolAddress((void**)&hA,   g_hA);
    cudaGetSymbolAddress((void**)&hB,   g_hB);
    cudaGetSymbolAddress((void**)&T1,   g_T1);
    cudaGetSymbolAddress((void**)&T2,   g_T2);
    cudaGetSymbolAddress((void**)&Msum, g_Msum);
    cudaGetSymbolAddress((void**)&usum, g_usum);

    // reverse-CSR build (by src); dinv from dst in-degree
    hist_kernel<<<(NE + 255) / 256, 256>>>(ei);                              // 0
    scan1_kernel<<<NB, 1024>>>();                                            // 1
    scan2_kernel<<<1, 256>>>();                                              // 2
    scan3_kernel<<<NB, 1024>>>();                                            // 3
    scatter_init_kernel<<<EDGE_BLOCKS + Q0_BLOCKS + ZQ_BLOCKS, 256>>>(ei, batch); // 4
    // q-hops: z0 -> z1 -> z2 -> q3 (column sums give u1 = PÂ1, u2 = PÂ²1)
    hop_kernel<<<NN / 4, 128>>>(hA, hB, 0);                                  // 5
    colsum_kernel<<<(NN + CS_ROWS - 1) / CS_ROWS, 256>>>(hB, usum);          // 6
    hop_kernel<<<NN / 4, 128>>>(hB, hA, 0);                                  // 7
    colsum_kernel<<<(NN + CS_ROWS - 1) / CS_ROWS, 256>>>(hA, usum + NG);     // 8
    hop_kernel<<<NN / 4, 128>>>(hA, hB, 1);                                  // 9 -> q3 in hB
    // factor through embedding tables: Msum = q3^T Ia at + q3^T Iw wt
    vscatter_kernel<<<(NN + VCH - 1) / VCH, 256>>>(hB, x);                   // 10
    vgemm_kernel<<<161, 320>>>(wt, at);                                      // 11
    // epilogue: ((Msum@W + u2⊗b)@W + u1⊗b)@W, then /cnt + b
    mg_kernel<<<NG, 320>>>(Msum, T1, W, b, usum + NG, 0);                    // 12
    mg_kernel<<<NG, 320>>>(T1,   T2, W, b, usum,      0);                    // 13
    mg_kernel<<<NG, 320>>>(T2,  out, W, b, usum,      1);                    // 14
}